// round 4
// baseline (speedup 1.0000x reference)
#include <cuda_runtime.h>
#include <math_constants.h>

// kNN graph, PyG knn_graph(loop=False): B=16 graphs x n=4096 pts, D=3, k=16.
// Output (float32 flat): [nbr_global | centers | topk_d2], each total_n*K,
// ordering (b*n+i)*K + m (matches reference reshape(-1)).

#define K        16
#define KP1      17            // keep k+1; self entry removed at output
#define NPER     4096
#define TPB      256
#define CPG      (NPER / TPB)  // 16 CTAs per graph
#define PB       16            // pending u64 slots per thread
#define FLUSH_AT 9             // flush when cnt >= 9 (room for 8 more pushes)
#define SLOT_STRIDE (TPB * 8)  // bytes between a thread's consecutive slots

#define FMA_F32X2(out, a, b, c) \
    asm("fma.rn.f32x2 %0, %1, %2, %3;" : "=l"(out) : "l"(a), "l"(b), "l"(c))
#define MUL_F32X2_(out, a, b) \
    asm("mul.rn.f32x2 %0, %1, %2;" : "=l"(out) : "l"(a), "l"(b))
#define ADD_F32X2_(out, a, b) \
    asm("add.rn.f32x2 %0, %1, %2;" : "=l"(out) : "l"(a), "l"(b))
#define PACK2(out, lo, hi) \
    asm("mov.b64 %0, {%1, %2};" : "=l"(out) : "r"(lo), "r"(hi))
#define UNPACK2(lo, hi, in) \
    asm("mov.b64 {%0, %1}, %2;" : "=r"(lo), "=r"(hi) : "l"(in))

// Branchless predicated FIFO push: if (d <= worstf) { store key; advance }.
// No BSSY/BSYNC — pure @p predication.
#define PUSH_CAND(dv, jv)                                                     \
    do {                                                                      \
        unsigned long long kk_;                                               \
        asm("mov.b64 %0, {%1, %2};"                                           \
            : "=l"(kk_) : "r"(jv), "r"(__float_as_uint(dv)));                 \
        asm volatile(                                                         \
            "{\n\t.reg .pred p;\n\t"                                          \
            "setp.le.f32 p, %2, %3;\n\t"                                      \
            "@p st.shared.b64 [%0], %1;\n\t"                                  \
            "@p add.u32 %0, %0, %4;\n\t}"                                     \
            : "+r"(aaddr)                                                     \
            : "l"(kk_), "f"(dv), "f"(worstf), "n"(SLOT_STRIDE)                \
            : "memory");                                                      \
    } while (0)

__global__ __launch_bounds__(TPB, 2)
void knn_topk_kernel(const float* __restrict__ pos,
                     float* __restrict__ out,
                     int total_n)
{
    extern __shared__ float smem[];
    float* sx = smem;
    float* sy = smem +     NPER;
    float* sz = smem + 2 * NPER;
    float* ss = smem + 3 * NPER;
    unsigned long long* pend =
        (unsigned long long*)(smem + 4 * NPER);   // [PB][TPB] pending keys

    const int graph = blockIdx.x / CPG;
    const int base  = graph * NPER;
    const float* gp = pos + (size_t)base * 3;

    // Stage graph points (SoA) + squared norms. ss uses the SAME op order as
    // the dot-product chain (x, then y, then z) so that the self-distance
    // d(q,q) = (qs+qs) - 2*dot(q,q) is exactly +0.
    for (int p = threadIdx.x; p < NPER; p += TPB) {
        float x = gp[3 * p + 0];
        float y = gp[3 * p + 1];
        float z = gp[3 * p + 2];
        sx[p] = x; sy[p] = y; sz[p] = z;
        ss[p] = fmaf(z, z, fmaf(y, y, x * x));
    }
    __syncthreads();

    const int   tid = threadIdx.x;
    const int   q   = (blockIdx.x % CPG) * TPB + tid;
    const float qx = sx[q], qy = sy[q], qz = sz[q], qs = ss[q];

    unsigned long long qx2, qy2, qz2, qs2, m2;
    {
        const unsigned xb = __float_as_uint(qx), yb = __float_as_uint(qy);
        const unsigned zb = __float_as_uint(qz), sb = __float_as_uint(qs);
        const unsigned nb = __float_as_uint(-2.0f);
        PACK2(qx2, xb, xb); PACK2(qy2, yb, yb); PACK2(qz2, zb, zb);
        PACK2(qs2, sb, sb); PACK2(m2, nb, nb);
    }

    // Sorted K+1 list of transformed (monotone dist bits, index) u64 keys.
    // INIT = (+inf transformed = 0xFF800000, idx 0xFFFFFFFF): > any real key.
    unsigned long long bk[KP1];
#pragma unroll
    for (int m = 0; m < KP1; ++m) bk[m] = 0xFF800000FFFFFFFFull;
    float worstf = CUDART_INF_F;

    // FIFO cursor: byte address of this thread's next free slot.
    const unsigned abase  = (unsigned)__cvta_generic_to_shared(pend + tid);
    unsigned       aaddr  = abase;
    const unsigned athresh = abase + FLUSH_AT * SLOT_STRIDE;

    for (int j0 = 0; j0 < NPER; j0 += 8) {
        const ulonglong2 Xa = *reinterpret_cast<const ulonglong2*>(sx + j0);
        const ulonglong2 Ya = *reinterpret_cast<const ulonglong2*>(sy + j0);
        const ulonglong2 Za = *reinterpret_cast<const ulonglong2*>(sz + j0);
        const ulonglong2 Sa = *reinterpret_cast<const ulonglong2*>(ss + j0);
        const ulonglong2 Xb = *reinterpret_cast<const ulonglong2*>(sx + j0 + 4);
        const ulonglong2 Yb = *reinterpret_cast<const ulonglong2*>(sy + j0 + 4);
        const ulonglong2 Zb = *reinterpret_cast<const ulonglong2*>(sz + j0 + 4);
        const ulonglong2 Sb = *reinterpret_cast<const ulonglong2*>(ss + j0 + 4);

        // d = (qs + s) - 2*dot; f32x2 = two independent fp32 FMAs with the
        // exact op order/rounding of the reference formula.
        unsigned long long dt, tt, dp0, dp1, dp2, dp3;
        MUL_F32X2_(dt, qx2, Xa.x); FMA_F32X2(dt, qy2, Ya.x, dt); FMA_F32X2(dt, qz2, Za.x, dt);
        ADD_F32X2_(tt, Sa.x, qs2); FMA_F32X2(dp0, m2, dt, tt);
        MUL_F32X2_(dt, qx2, Xa.y); FMA_F32X2(dt, qy2, Ya.y, dt); FMA_F32X2(dt, qz2, Za.y, dt);
        ADD_F32X2_(tt, Sa.y, qs2); FMA_F32X2(dp1, m2, dt, tt);
        MUL_F32X2_(dt, qx2, Xb.x); FMA_F32X2(dt, qy2, Yb.x, dt); FMA_F32X2(dt, qz2, Zb.x, dt);
        ADD_F32X2_(tt, Sb.x, qs2); FMA_F32X2(dp2, m2, dt, tt);
        MUL_F32X2_(dt, qx2, Xb.y); FMA_F32X2(dt, qy2, Yb.y, dt); FMA_F32X2(dt, qz2, Zb.y, dt);
        ADD_F32X2_(tt, Sb.y, qs2); FMA_F32X2(dp3, m2, dt, tt);

        unsigned u0, u1, u2, u3, u4, u5, u6, u7;
        UNPACK2(u0, u1, dp0); UNPACK2(u2, u3, dp1);
        UNPACK2(u4, u5, dp2); UNPACK2(u6, u7, dp3);
        const float d0 = __uint_as_float(u0), d1 = __uint_as_float(u1);
        const float d2 = __uint_as_float(u2), d3 = __uint_as_float(u3);
        const float d4 = __uint_as_float(u4), d5 = __uint_as_float(u5);
        const float d6 = __uint_as_float(u6), d7 = __uint_as_float(u7);

        const float mn = fminf(fminf(fminf(d0, d1), fminf(d2, d3)),
                               fminf(fminf(d4, d5), fminf(d6, d7)));
        // '<=' so boundary ties (same d, lower index) still enter; the u64
        // key compare in the chain decides exactly.
        if (__any_sync(0xFFFFFFFFu, mn <= worstf)) {
            PUSH_CAND(d0, j0 + 0);
            PUSH_CAND(d1, j0 + 1);
            PUSH_CAND(d2, j0 + 2);
            PUSH_CAND(d3, j0 + 3);
            PUSH_CAND(d4, j0 + 4);
            PUSH_CAND(d5, j0 + 5);
            PUSH_CAND(d6, j0 + 6);
            PUSH_CAND(d7, j0 + 7);
        }

        // Warp-synchronized flush.
        if (__any_sync(0xFFFFFFFFu, aaddr >= athresh)) {
            const int cnt  = (int)((aaddr - abase) / SLOT_STRIDE);
            const int wmax = __reduce_max_sync(0xFFFFFFFFu, cnt);
            const unsigned long long* myp = pend + tid;
#pragma unroll 1
            for (int p = 0; p < wmax; ++p) {
                unsigned long long kk = myp[(size_t)p * TPB];
                // monotone transform of the distance bits (handles the tiny
                // negative d from rounding on near-duplicate points)
                unsigned hi = (unsigned)(kk >> 32);
                unsigned lo = (unsigned)kk;
                hi ^= (unsigned)(((int)hi >> 31)) | 0x80000000u;
                kk = ((unsigned long long)hi << 32) | lo;
                kk = (p < cnt) ? kk : ~0ull;   // masked slots fall off the end
#pragma unroll
                for (int m = 0; m < KP1; ++m) {
                    const bool sw = kk < bk[m];     // ties keep lower index
                    const unsigned long long lokey = sw ? kk : bk[m];
                    kk    = sw ? bk[m] : kk;
                    bk[m] = lokey;
                }
            }
            aaddr = abase;
            const unsigned wh = (unsigned)(bk[KP1 - 1] >> 32);
            const unsigned wu = (wh & 0x80000000u) ? (wh ^ 0x80000000u) : ~wh;
            worstf = __uint_as_float(wu);
        }
    }

    // Final drain of residual pending entries.
    {
        const int cnt  = (int)((aaddr - abase) / SLOT_STRIDE);
        const int wmax = __reduce_max_sync(0xFFFFFFFFu, cnt);
        const unsigned long long* myp = pend + tid;
#pragma unroll 1
        for (int p = 0; p < wmax; ++p) {
            unsigned long long kk = myp[(size_t)p * TPB];
            unsigned hi = (unsigned)(kk >> 32);
            unsigned lo = (unsigned)kk;
            hi ^= (unsigned)(((int)hi >> 31)) | 0x80000000u;
            kk = ((unsigned long long)hi << 32) | lo;
            kk = (p < cnt) ? kk : ~0ull;
#pragma unroll
            for (int m = 0; m < KP1; ++m) {
                const bool sw = kk < bk[m];
                const unsigned long long lokey = sw ? kk : bk[m];
                kk    = sw ? bk[m] : kk;
                bk[m] = lokey;
            }
        }
    }

    // Emit: skip the self entry (exactly one, d == +0), keep first K others.
    const int    gq = base + q;
    const size_t Nk = (size_t)total_n * K;
    int w = 0;
#pragma unroll
    for (int m = 0; m < KP1; ++m) {
        const int      idx = (int)(unsigned)bk[m];
        const unsigned hi  = (unsigned)(bk[m] >> 32);
        const unsigned du  = (hi & 0x80000000u) ? (hi ^ 0x80000000u) : ~hi;
        if (idx != q && w < K) {
            const size_t e = (size_t)gq * K + w;
            out[e]          = (float)(idx + base);
            out[Nk + e]     = (float)gq;
            out[2 * Nk + e] = __uint_as_float(du);
            ++w;
        }
    }
}

extern "C" void kernel_launch(void* const* d_in, const int* in_sizes, int n_in,
                              void* d_out, int out_size)
{
    const float* pos = (const float*)d_in[0];
    const int total_n = in_sizes[0] / 3;
    const int ngraphs = total_n / NPER;

    const int smem_bytes = 4 * NPER * (int)sizeof(float)
                         + PB * TPB * (int)sizeof(unsigned long long); // 96 KB
    cudaFuncSetAttribute(knn_topk_kernel,
                         cudaFuncAttributeMaxDynamicSharedMemorySize, smem_bytes);

    knn_topk_kernel<<<ngraphs * CPG, TPB, smem_bytes>>>(pos, (float*)d_out, total_n);
}